// round 1
// baseline (speedup 1.0000x reference)
#include <cuda_runtime.h>
#include <math.h>

#define B_  4
#define L_  2048
#define D_  2048
#define H_  16
#define HD  128
#define BH  (B_*H_)

// ---------------- device scratch (allocation-free rule: __device__ globals) ----
__device__ float g_q[(size_t)BH * L_ * HD];     // (B,H,L,d) 64MB
__device__ float g_k[(size_t)BH * L_ * HD];     // (B,H,L,d) 64MB
__device__ float g_v[(size_t)BH * L_ * HD];     // (B,H,L,d) 64MB
__device__ float g_att[(size_t)B_ * L_ * D_];   // (B,L,H,d) 64MB
__device__ float g_qsq[BH * L_];
__device__ float g_ksq[BH * L_];
__device__ float g_cos[L_ * 64];
__device__ float g_sin[L_ * 64];

// ---------------- RoPE tables (double-precision truth) ------------------------
__global__ void rope_table_kernel() {
    int l = blockIdx.x;
    int i = threadIdx.x;                       // 0..63
    double invf = exp(((double)(-2 * i) / 128.0) * log(10000.0));
    double th = (double)l * invf;
    double s, c;
    sincos(th, &s, &c);
    g_cos[l * 64 + i] = (float)c;
    g_sin[l * 64 + i] = (float)s;
}

// ---------------- SGEMM core: C = A(MxK) * W(NxK)^T, 128x128 tile, 8x8 micro ---
#define BM 128
#define BN 128
#define BK 16
#define SAP 132   // padded smem row stride (2-way max conflict)

__device__ __forceinline__ void sgemm_compute(const float* __restrict__ A,
                                              const float* __restrict__ W,
                                              int K, int bm, int bn,
                                              float (&acc)[8][8]) {
    __shared__ float As[BK][SAP];
    __shared__ float Ws[BK][SAP];
    const int tid = threadIdx.x;
    const int tx = tid & 15, ty = tid >> 4;
    const int ar = tid >> 2;              // 0..63
    const int ac = (tid & 3) << 2;        // 0,4,8,12

#pragma unroll
    for (int i = 0; i < 8; i++)
#pragma unroll
        for (int j = 0; j < 8; j++) acc[i][j] = 0.f;

    for (int k0 = 0; k0 < K; k0 += BK) {
#pragma unroll
        for (int i = 0; i < 2; i++) {
            int r = ar + i * 64;
            float4 va = *(const float4*)(A + (size_t)(bm + r) * K + k0 + ac);
            As[ac + 0][r] = va.x; As[ac + 1][r] = va.y;
            As[ac + 2][r] = va.z; As[ac + 3][r] = va.w;
            float4 vw = *(const float4*)(W + (size_t)(bn + r) * K + k0 + ac);
            Ws[ac + 0][r] = vw.x; Ws[ac + 1][r] = vw.y;
            Ws[ac + 2][r] = vw.z; Ws[ac + 3][r] = vw.w;
        }
        __syncthreads();
#pragma unroll
        for (int kk = 0; kk < BK; kk++) {
            float a[8], b[8];
            *(float4*)&a[0] = *(const float4*)&As[kk][ty * 8];
            *(float4*)&a[4] = *(const float4*)&As[kk][ty * 8 + 4];
            *(float4*)&b[0] = *(const float4*)&Ws[kk][tx * 8];
            *(float4*)&b[4] = *(const float4*)&Ws[kk][tx * 8 + 4];
#pragma unroll
            for (int i = 0; i < 8; i++)
#pragma unroll
                for (int j = 0; j < 8; j++)
                    acc[i][j] = fmaf(a[i], b[j], acc[i][j]);
        }
        __syncthreads();
    }
}

// QKV projection: y = x @ W^T, stored remapped to (B,H,L,d)
__global__ void __launch_bounds__(256) sgemm_qkv_kernel(const float* __restrict__ x,
                                                        const float* __restrict__ Wq,
                                                        const float* __restrict__ Wk,
                                                        const float* __restrict__ Wv) {
    const int z = blockIdx.z;
    const float* W = (z == 0) ? Wq : (z == 1) ? Wk : Wv;
    float* dst = (z == 0) ? g_q : (z == 1) ? g_k : g_v;
    float acc[8][8];
    const int bm = blockIdx.y * BM, bn = blockIdx.x * BN;
    sgemm_compute(x, W, D_, bm, bn, acc);

    const int tx = threadIdx.x & 15, ty = threadIdx.x >> 4;
    const int n0 = bn + tx * 8;
    const int h = n0 >> 7, jj = n0 & 127;
#pragma unroll
    for (int i = 0; i < 8; i++) {
        int m = bm + ty * 8 + i;
        int bb = m >> 11, l = m & 2047;
        size_t off = (((size_t)(bb * H_ + h) * L_ + l) * HD) + jj;
        *(float4*)&dst[off]     = make_float4(acc[i][0], acc[i][1], acc[i][2], acc[i][3]);
        *(float4*)&dst[off + 4] = make_float4(acc[i][4], acc[i][5], acc[i][6], acc[i][7]);
    }
}

// Output projection: out = att @ Wo^T (plain row-major store)
__global__ void __launch_bounds__(256) sgemm_out_kernel(const float* __restrict__ Wo,
                                                        float* __restrict__ C) {
    float acc[8][8];
    const int bm = blockIdx.y * BM, bn = blockIdx.x * BN;
    sgemm_compute(g_att, Wo, D_, bm, bn, acc);

    const int tx = threadIdx.x & 15, ty = threadIdx.x >> 4;
#pragma unroll
    for (int i = 0; i < 8; i++) {
        size_t m = (size_t)bm + ty * 8 + i;
        size_t off = m * D_ + bn + tx * 8;
        *(float4*)&C[off]     = make_float4(acc[i][0], acc[i][1], acc[i][2], acc[i][3]);
        *(float4*)&C[off + 4] = make_float4(acc[i][4], acc[i][5], acc[i][6], acc[i][7]);
    }
}

// ---------------- RoPE + sigmoid + row sum-of-squares --------------------------
__global__ void rope_kernel() {
    const int l = blockIdx.x, bh = blockIdx.y, j = threadIdx.x;
    const size_t base = ((size_t)bh * L_ + l) * HD;
    const float c = g_cos[l * 64 + (j & 63)];
    const float s = g_sin[l * 64 + (j & 63)];

    __shared__ float qr[128], kr[128];
    float qv = g_q[base + j], kv = g_k[base + j];
    qr[j] = qv; kr[j] = kv;
    __syncthreads();
    float qpart = (j < 64) ? -qr[j + 64] : qr[j - 64];
    float kpart = (j < 64) ? -kr[j + 64] : kr[j - 64];
    float qo = qv * c + qpart * s;
    float ko = kv * c + kpart * s;
    float qt = 1.f / (1.f + expf(-qo));
    float kt = 1.f / (1.f + expf(-ko));
    g_q[base + j] = qt;
    g_k[base + j] = kt;

    float q2 = qt * qt, k2 = kt * kt;
#pragma unroll
    for (int o = 16; o; o >>= 1) {
        q2 += __shfl_xor_sync(0xffffffffu, q2, o);
        k2 += __shfl_xor_sync(0xffffffffu, k2, o);
    }
    __shared__ float rq[4], rk[4];
    if ((j & 31) == 0) { rq[j >> 5] = q2; rk[j >> 5] = k2; }
    __syncthreads();
    if (j == 0) g_qsq[(size_t)bh * L_ + l] = rq[0] + rq[1] + rq[2] + rq[3];
    if (j == 1) g_ksq[(size_t)bh * L_ + l] = rk[0] + rk[1] + rk[2] + rk[3];
}

// ---------------- causal flash attention ---------------------------------------
// TQ=128 q rows per block, TK=64 k cols per tile. 256 threads: tx=tid&7 (S cols
// x8), ty=tid>>3 (S rows x4). O per thread: 4 rows x 16 cols.
#define QS_STR 132
#define KS_STR 68
#define VS_STR 128
#define PS_STR 68
#define FLASH_SMEM ((128*QS_STR + 128*KS_STR + 64*VS_STR + 128*PS_STR + 128 + 64) * 4)

__global__ void __launch_bounds__(256) flash_kernel(const float* __restrict__ tau_p) {
    extern __shared__ float sm[];
    float* Qs  = sm;                    // [128][132] transposed: Qs[kk][r]
    float* Ks  = Qs + 128 * QS_STR;     // [128][68]  transposed: Ks[kk][c]
    float* Vs  = Ks + 128 * KS_STR;     // [64][128]  natural:    Vs[k][c]
    float* Ps  = Vs + 64 * VS_STR;      // [128][68]  natural:    Ps[r][c]
    float* sqs = Ps + 128 * PS_STR;     // [128]
    float* sks = sqs + 128;             // [64]

    const int qi = blockIdx.x;          // q tile 0..15
    const int bh = blockIdx.y;          // 0..63
    const int b = bh >> 4, h = bh & 15;
    const int tid = threadIdx.x;
    const int lane = tid & 31, warp = tid >> 5;
    const int tx = tid & 7, ty = tid >> 3;

    float tr = tau_p[0];
    float tau = log1pf(expf(tr));
    tau = fminf(fmaxf(tau, 0.1f), 10.f);
    const float inv_tau = 1.f / tau;

    const size_t hbase = (size_t)bh * L_ * HD;
    const float* Qg = g_q + hbase + (size_t)qi * 128 * HD;

    // load Q tile transposed into smem
    {
        const int rl = lane >> 2;                  // 0..7
        const int c4 = (warp << 2) + (lane & 3);   // 0..31
#pragma unroll
        for (int rep = 0; rep < 16; rep++) {
            int r = rep * 8 + rl;
            float4 v = *(const float4*)(Qg + (size_t)r * HD + c4 * 4);
            Qs[(c4 * 4 + 0) * QS_STR + r] = v.x;
            Qs[(c4 * 4 + 1) * QS_STR + r] = v.y;
            Qs[(c4 * 4 + 2) * QS_STR + r] = v.z;
            Qs[(c4 * 4 + 3) * QS_STR + r] = v.w;
        }
    }
    if (tid < 128) sqs[tid] = g_qsq[(size_t)bh * L_ + qi * 128 + tid];

    float m_i[4], l_i[4], O[4][16];
#pragma unroll
    for (int i = 0; i < 4; i++) {
        m_i[i] = -INFINITY; l_i[i] = 0.f;
#pragma unroll
        for (int cc = 0; cc < 16; cc++) O[i][cc] = 0.f;
    }

    const int ntk = 2 * qi + 2;   // k tiles needed for causal coverage
    for (int kt = 0; kt < ntk; kt++) {
        const int j0 = kt * 64;
        __syncthreads();  // prev PV done (and Q load on first iter) before overwrite

        // load K tile transposed
        {
            const int rl = lane >> 2;
            const int c4 = (warp << 2) + (lane & 3);
            const float* Kg = g_k + hbase + (size_t)j0 * HD;
#pragma unroll
            for (int rep = 0; rep < 8; rep++) {
                int r = rep * 8 + rl;   // k row = S col
                float4 v = *(const float4*)(Kg + (size_t)r * HD + c4 * 4);
                Ks[(c4 * 4 + 0) * KS_STR + r] = v.x;
                Ks[(c4 * 4 + 1) * KS_STR + r] = v.y;
                Ks[(c4 * 4 + 2) * KS_STR + r] = v.z;
                Ks[(c4 * 4 + 3) * KS_STR + r] = v.w;
            }
        }
        // load V tile natural
        {
            const float* Vg = g_v + hbase + (size_t)j0 * HD;
#pragma unroll
            for (int rep = 0; rep < 8; rep++) {
                int idx = rep * 256 + tid;
                int k = idx >> 5, c4 = idx & 31;
                *(float4*)&Vs[k * VS_STR + c4 * 4] =
                    *(const float4*)(Vg + (size_t)k * HD + c4 * 4);
            }
        }
        if (tid < 64) sks[tid] = g_ksq[(size_t)bh * L_ + j0 + tid];
        __syncthreads();

        // S = Qt . Kt^T  (128 x 64)
        float s[4][8];
#pragma unroll
        for (int i = 0; i < 4; i++)
#pragma unroll
            for (int j = 0; j < 8; j++) s[i][j] = 0.f;

#pragma unroll 8
        for (int kk = 0; kk < 128; kk++) {
            float4 qa  = *(const float4*)&Qs[kk * QS_STR + ty * 4];
            float4 kb0 = *(const float4*)&Ks[kk * KS_STR + tx * 8];
            float4 kb1 = *(const float4*)&Ks[kk * KS_STR + tx * 8 + 4];
            float a[4] = {qa.x, qa.y, qa.z, qa.w};
            float bb[8] = {kb0.x, kb0.y, kb0.z, kb0.w, kb1.x, kb1.y, kb1.z, kb1.w};
#pragma unroll
            for (int i = 0; i < 4; i++)
#pragma unroll
                for (int j = 0; j < 8; j++)
                    s[i][j] = fmaf(a[i], bb[j], s[i][j]);
        }

        // score transform + online softmax update
#pragma unroll
        for (int i = 0; i < 4; i++) {
            const int gq_ = qi * 128 + ty * 4 + i;
            const float qs = sqs[ty * 4 + i];
            float rm = -INFINITY;
#pragma unroll
            for (int j = 0; j < 8; j++) {
                int gk = j0 + tx * 8 + j;
                float sc = (2.f * s[i][j] - qs - sks[tx * 8 + j]) * inv_tau;
                sc = (gk > gq_) ? -INFINITY : sc;
                s[i][j] = sc;
                rm = fmaxf(rm, sc);
            }
            rm = fmaxf(rm, __shfl_xor_sync(0xffffffffu, rm, 1));
            rm = fmaxf(rm, __shfl_xor_sync(0xffffffffu, rm, 2));
            rm = fmaxf(rm, __shfl_xor_sync(0xffffffffu, rm, 4));
            float mnew = fmaxf(m_i[i], rm);
            float scale = __expf(m_i[i] - mnew);
            float rs = 0.f;
#pragma unroll
            for (int j = 0; j < 8; j++) {
                float p = __expf(s[i][j] - mnew);
                s[i][j] = p; rs += p;
            }
            rs += __shfl_xor_sync(0xffffffffu, rs, 1);
            rs += __shfl_xor_sync(0xffffffffu, rs, 2);
            rs += __shfl_xor_sync(0xffffffffu, rs, 4);
            l_i[i] = l_i[i] * scale + rs;
            m_i[i] = mnew;
#pragma unroll
            for (int cc = 0; cc < 16; cc++) O[i][cc] *= scale;
            *(float4*)&Ps[(ty * 4 + i) * PS_STR + tx * 8] =
                make_float4(s[i][0], s[i][1], s[i][2], s[i][3]);
            *(float4*)&Ps[(ty * 4 + i) * PS_STR + tx * 8 + 4] =
                make_float4(s[i][4], s[i][5], s[i][6], s[i][7]);
        }
        __syncthreads();

        // O += P . V
#pragma unroll 4
        for (int k = 0; k < 64; k++) {
            float4 v0 = *(const float4*)&Vs[k * VS_STR + tx * 16];
            float4 v1 = *(const float4*)&Vs[k * VS_STR + tx * 16 + 4];
            float4 v2 = *(const float4*)&Vs[k * VS_STR + tx * 16 + 8];
            float4 v3 = *(const float4*)&Vs[k * VS_STR + tx * 16 + 12];
            float vv[16] = {v0.x, v0.y, v0.z, v0.w, v1.x, v1.y, v1.z, v1.w,
                            v2.x, v2.y, v2.z, v2.w, v3.x, v3.y, v3.z, v3.w};
#pragma unroll
            for (int i = 0; i < 4; i++) {
                float p = Ps[(ty * 4 + i) * PS_STR + k];
#pragma unroll
                for (int cc = 0; cc < 16; cc++)
                    O[i][cc] = fmaf(p, vv[cc], O[i][cc]);
            }
        }
    }

    // normalize + store to (B, L, H, d)
#pragma unroll
    for (int i = 0; i < 4; i++) {
        float invl = 1.f / l_i[i];
        int gq_ = qi * 128 + ty * 4 + i;
        size_t off = (((size_t)b * L_ + gq_) * H_ + h) * HD + tx * 16;
        *(float4*)&g_att[off]      = make_float4(O[i][0] * invl,  O[i][1] * invl,
                                                 O[i][2] * invl,  O[i][3] * invl);
        *(float4*)&g_att[off + 4]  = make_float4(O[i][4] * invl,  O[i][5] * invl,
                                                 O[i][6] * invl,  O[i][7] * invl);
        *(float4*)&g_att[off + 8]  = make_float4(O[i][8] * invl,  O[i][9] * invl,
                                                 O[i][10] * invl, O[i][11] * invl);
        *(float4*)&g_att[off + 12] = make_float4(O[i][12] * invl, O[i][13] * invl,
                                                 O[i][14] * invl, O[i][15] * invl);
    }
}

// ---------------- launch --------------------------------------------------------
extern "C" void kernel_launch(void* const* d_in, const int* in_sizes, int n_in,
                              void* d_out, int out_size) {
    const float* x   = (const float*)d_in[0];
    const float* Wq  = (const float*)d_in[1];
    const float* Wk  = (const float*)d_in[2];
    const float* Wv  = (const float*)d_in[3];
    const float* Wo  = (const float*)d_in[4];
    const float* tau = (const float*)d_in[5];
    // d_in[6] = mask: exactly causal tril(0 / -inf) -> applied analytically
    float* out = (float*)d_out;

    cudaFuncSetAttribute(flash_kernel, cudaFuncAttributeMaxDynamicSharedMemorySize,
                         FLASH_SMEM);

    rope_table_kernel<<<L_, 64>>>();
    sgemm_qkv_kernel<<<dim3(D_ / BN, (B_ * L_) / BM, 3), 256>>>(x, Wq, Wk, Wv);
    rope_kernel<<<dim3(L_, BH), 128>>>();
    flash_kernel<<<dim3(L_ / 128, BH), 256, FLASH_SMEM>>>(tau);
    sgemm_out_kernel<<<dim3(D_ / BN, (B_ * L_) / BM), 256>>>(Wo, out);
}

// round 7
// speedup vs baseline: 1.3954x; 1.3954x over previous
#include <cuda_runtime.h>
#include <math.h>
#include <stdint.h>

#define B_  4
#define L_  2048
#define D_  2048
#define H_  16
#define HD  128
#define BH  (B_*H_)

// ---------------- device scratch (allocation-free rule: __device__ globals) ----
__device__ float g_q[(size_t)BH * L_ * HD];     // (B,H,L,d)
__device__ float g_k[(size_t)BH * L_ * HD];     // (B,H,L,d)
__device__ float g_v[(size_t)BH * L_ * HD];     // (B,H,L,d)
__device__ float g_att[(size_t)B_ * L_ * D_];   // (B,L,H,d)
__device__ float g_qsq[BH * L_];
__device__ float g_ksq[BH * L_];
__device__ float g_cos[L_ * 64];
__device__ float g_sin[L_ * 64];

// ---------------- mma.sync helpers ---------------------------------------------
__device__ __forceinline__ uint32_t f2tf32(float x) {
    uint32_t r;
    asm("cvt.rna.tf32.f32 %0, %1;" : "=r"(r) : "f"(x));
    return r;
}
__device__ __forceinline__ void mma_tf32(float (&d)[4], const uint32_t (&a)[4],
                                         uint32_t b0, uint32_t b1) {
    asm volatile(
        "mma.sync.aligned.m16n8k8.row.col.f32.tf32.tf32.f32 "
        "{%0,%1,%2,%3}, {%4,%5,%6,%7}, {%8,%9}, {%0,%1,%2,%3};"
        : "+f"(d[0]), "+f"(d[1]), "+f"(d[2]), "+f"(d[3])
        : "r"(a[0]), "r"(a[1]), "r"(a[2]), "r"(a[3]), "r"(b0), "r"(b1));
}

// ---------------- RoPE tables (double-precision truth) ------------------------
__global__ void rope_table_kernel() {
    int l = blockIdx.x;
    int i = threadIdx.x;                       // 0..63
    double invf = exp(((double)(-2 * i) / 128.0) * log(10000.0));
    double th = (double)l * invf;
    double s, c;
    sincos(th, &s, &c);
    g_cos[l * 64 + i] = (float)c;
    g_sin[l * 64 + i] = (float)s;
}

// ---------------- GEMM core: C = A(MxK) * W(NxK)^T via mma.sync tf32 ------------
// Structure kept IDENTICAL to the R1-proven sgemm (static shared, 256 threads,
// 128x128 CTA tile, synchronous float4 loader with transposed smem store).
// Only the inner product uses tensor cores: 8 warps in a 4x2 grid, each warp
// owns m32 x n64 via m16n8k8 tf32 MMAs.
#define BM 128
#define BN 128
#define BK 32
#define SAP 132   // padded smem row stride

__device__ __forceinline__ void sgemm_compute_mma(const float* __restrict__ A,
                                                  const float* __restrict__ W,
                                                  int K, int bm, int bn,
                                                  float (&acc)[2][8][4]) {
    __shared__ float As[BK][SAP];   // As[k][row]
    __shared__ float Ws[BK][SAP];   // Ws[k][col]
    const int tid  = threadIdx.x;
    const int warp = tid >> 5, lane = tid & 31;
    const int wm = warp >> 1, wn = warp & 1;            // 4 x 2 warp grid
    const int wm0 = wm * 32, wn0 = wn * 64;
    const int lr = lane >> 2;                           // 0..7
    const int lc = lane & 3;                            // 0..3

#pragma unroll
    for (int mt = 0; mt < 2; mt++)
#pragma unroll
        for (int nt = 0; nt < 8; nt++)
#pragma unroll
            for (int i = 0; i < 4; i++) acc[mt][nt][i] = 0.f;

    for (int k0 = 0; k0 < K; k0 += BK) {
        __syncthreads();   // prior compute done before overwrite
        // loader: 128 rows x 8 float4 per matrix; 256 threads x 4 slots each
#pragma unroll
        for (int p = 0; p < 4; p++) {
            int idx = tid + p * 256;
            int r  = idx >> 3;              // 0..127
            int c4 = (idx & 7) << 2;        // 0,4,...,28
            float4 va = *(const float4*)(A + (size_t)(bm + r) * K + k0 + c4);
            As[c4 + 0][r] = va.x; As[c4 + 1][r] = va.y;
            As[c4 + 2][r] = va.z; As[c4 + 3][r] = va.w;
            float4 vw = *(const float4*)(W + (size_t)(bn + r) * K + k0 + c4);
            Ws[c4 + 0][r] = vw.x; Ws[c4 + 1][r] = vw.y;
            Ws[c4 + 2][r] = vw.z; Ws[c4 + 3][r] = vw.w;
        }
        __syncthreads();

#pragma unroll
        for (int ks = 0; ks < BK / 8; ks++) {
            const int kb = ks * 8;
            uint32_t a[2][4];
#pragma unroll
            for (int mt = 0; mt < 2; mt++) {
                const int r = wm0 + mt * 16 + lr;
                a[mt][0] = f2tf32(As[kb + lc][r]);
                a[mt][1] = f2tf32(As[kb + lc][r + 8]);
                a[mt][2] = f2tf32(As[kb + lc + 4][r]);
                a[mt][3] = f2tf32(As[kb + lc + 4][r + 8]);
            }
#pragma unroll
            for (int nt = 0; nt < 8; nt++) {
                const int n = wn0 + nt * 8 + lr;
                uint32_t b0 = f2tf32(Ws[kb + lc][n]);
                uint32_t b1 = f2tf32(Ws[kb + lc + 4][n]);
                mma_tf32(acc[0][nt], a[0], b0, b1);
                mma_tf32(acc[1][nt], a[1], b0, b1);
            }
        }
    }
}

// QKV projection: y = x @ W^T, stored remapped to (B,H,L,d)
__global__ void __launch_bounds__(256) sgemm_qkv_kernel(const float* __restrict__ x,
                                                        const float* __restrict__ Wq,
                                                        const float* __restrict__ Wk,
                                                        const float* __restrict__ Wv) {
    const int z = blockIdx.z;
    const float* W = (z == 0) ? Wq : (z == 1) ? Wk : Wv;
    float* dst = (z == 0) ? g_q : (z == 1) ? g_k : g_v;
    float acc[2][8][4];
    const int bm = blockIdx.y * BM, bn = blockIdx.x * BN;
    sgemm_compute_mma(x, W, D_, bm, bn, acc);

    const int warp = threadIdx.x >> 5, lane = threadIdx.x & 31;
    const int wm0 = (warp >> 1) * 32, wn0 = (warp & 1) * 64;
    const int lr = lane >> 2, lc = lane & 3;
    const int h = bn >> 7;                      // 128-wide N tile == one head
#pragma unroll
    for (int mt = 0; mt < 2; mt++) {
        const int mlo = bm + wm0 + mt * 16 + lr;
#pragma unroll
        for (int nt = 0; nt < 8; nt++) {
            const int jj = wn0 + nt * 8 + 2 * lc;   // 0..126
#pragma unroll
            for (int half = 0; half < 2; half++) {
                const int m = mlo + half * 8;
                const int bb = m >> 11, l = m & 2047;
                float* p = dst + (((size_t)(bb * H_ + h) * L_ + l) * HD + jj);
                *(float2*)p = make_float2(acc[mt][nt][half * 2],
                                          acc[mt][nt][half * 2 + 1]);
            }
        }
    }
}

// Output projection: out = att @ Wo^T (plain row-major store)
__global__ void __launch_bounds__(256) sgemm_out_kernel(const float* __restrict__ Wo,
                                                        float* __restrict__ C) {
    float acc[2][8][4];
    const int bm = blockIdx.y * BM, bn = blockIdx.x * BN;
    sgemm_compute_mma(g_att, Wo, D_, bm, bn, acc);

    const int warp = threadIdx.x >> 5, lane = threadIdx.x & 31;
    const int wm0 = (warp >> 1) * 32, wn0 = (warp & 1) * 64;
    const int lr = lane >> 2, lc = lane & 3;
#pragma unroll
    for (int mt = 0; mt < 2; mt++) {
        const int mlo = bm + wm0 + mt * 16 + lr;
#pragma unroll
        for (int nt = 0; nt < 8; nt++) {
            const int n0 = bn + wn0 + nt * 8 + 2 * lc;
#pragma unroll
            for (int half = 0; half < 2; half++) {
                const size_t m = mlo + half * 8;
                *(float2*)(C + m * D_ + n0) = make_float2(acc[mt][nt][half * 2],
                                                          acc[mt][nt][half * 2 + 1]);
            }
        }
    }
}

// ---------------- RoPE + sigmoid + row sum-of-squares --------------------------
__global__ void rope_kernel() {
    const int l = blockIdx.x, bh = blockIdx.y, j = threadIdx.x;
    const size_t base = ((size_t)bh * L_ + l) * HD;
    const float c = g_cos[l * 64 + (j & 63)];
    const float s = g_sin[l * 64 + (j & 63)];

    __shared__ float qr[128], kr[128];
    float qv = g_q[base + j], kv = g_k[base + j];
    qr[j] = qv; kr[j] = kv;
    __syncthreads();
    float qpart = (j < 64) ? -qr[j + 64] : qr[j - 64];
    float kpart = (j < 64) ? -kr[j + 64] : kr[j - 64];
    float qo = qv * c + qpart * s;
    float ko = kv * c + kpart * s;
    float qt = 1.f / (1.f + expf(-qo));
    float kt = 1.f / (1.f + expf(-ko));
    g_q[base + j] = qt;
    g_k[base + j] = kt;

    float q2 = qt * qt, k2 = kt * kt;
#pragma unroll
    for (int o = 16; o; o >>= 1) {
        q2 += __shfl_xor_sync(0xffffffffu, q2, o);
        k2 += __shfl_xor_sync(0xffffffffu, k2, o);
    }
    __shared__ float rq[4], rk[4];
    if ((j & 31) == 0) { rq[j >> 5] = q2; rk[j >> 5] = k2; }
    __syncthreads();
    if (j == 0) g_qsq[(size_t)bh * L_ + l] = rq[0] + rq[1] + rq[2] + rq[3];
    if (j == 1) g_ksq[(size_t)bh * L_ + l] = rk[0] + rk[1] + rk[2] + rk[3];
}

// ---------------- causal flash attention (fp32, proven R1) ----------------------
#define QS_STR 132
#define KS_STR 68
#define VS_STR 128
#define PS_STR 68
#define FLASH_SMEM ((128*QS_STR + 128*KS_STR + 64*VS_STR + 128*PS_STR + 128 + 64) * 4)

__global__ void __launch_bounds__(256) flash_kernel(const float* __restrict__ tau_p) {
    extern __shared__ float sm[];
    float* Qs  = sm;
    float* Ks  = Qs + 128 * QS_STR;
    float* Vs  = Ks + 128 * KS_STR;
    float* Ps  = Vs + 64 * VS_STR;
    float* sqs = Ps + 128 * PS_STR;
    float* sks = sqs + 128;

    const int qi = blockIdx.x;
    const int bh = blockIdx.y;
    const int b = bh >> 4, h = bh & 15;
    const int tid = threadIdx.x;
    const int lane = tid & 31, warp = tid >> 5;
    const int tx = tid & 7, ty = tid >> 3;

    float tr = tau_p[0];
    float tau = log1pf(expf(tr));
    tau = fminf(fmaxf(tau, 0.1f), 10.f);
    const float inv_tau = 1.f / tau;

    const size_t hbase = (size_t)bh * L_ * HD;
    const float* Qg = g_q + hbase + (size_t)qi * 128 * HD;

    {
        const int rl = lane >> 2;
        const int c4 = (warp << 2) + (lane & 3);
#pragma unroll
        for (int rep = 0; rep < 16; rep++) {
            int r = rep * 8 + rl;
            float4 v = *(const float4*)(Qg + (size_t)r * HD + c4 * 4);
            Qs[(c4 * 4 + 0) * QS_STR + r] = v.x;
            Qs[(c4 * 4 + 1) * QS_STR + r] = v.y;
            Qs[(c4 * 4 + 2) * QS_STR + r] = v.z;
            Qs[(c4 * 4 + 3) * QS_STR + r] = v.w;
        }
    }
    if (tid < 128) sqs[tid] = g_qsq[(size_t)bh * L_ + qi * 128 + tid];

    float m_i[4], l_i[4], O[4][16];
#pragma unroll
    for (int i = 0; i < 4; i++) {
        m_i[i] = -INFINITY; l_i[i] = 0.f;
#pragma unroll
        for (int cc = 0; cc < 16; cc++) O[i][cc] = 0.f;
    }

    const int ntk = 2 * qi + 2;
    for (int kt = 0; kt < ntk; kt++) {
        const int j0 = kt * 64;
        __syncthreads();

        {
            const int rl = lane >> 2;
            const int c4 = (warp << 2) + (lane & 3);
            const float* Kg = g_k + hbase + (size_t)j0 * HD;
#pragma unroll
            for (int rep = 0; rep < 8; rep++) {
                int r = rep * 8 + rl;
                float4 v = *(const float4*)(Kg + (size_t)r * HD + c4 * 4);
                Ks[(c4 * 4 + 0) * KS_STR + r] = v.x;
                Ks[(c4 * 4 + 1) * KS_STR + r] = v.y;
                Ks[(c4 * 4 + 2) * KS_STR + r] = v.z;
                Ks[(c4 * 4 + 3) * KS_STR + r] = v.w;
            }
        }
        {
            const float* Vg = g_v + hbase + (size_t)j0 * HD;
#pragma unroll
            for (int rep = 0; rep < 8; rep++) {
                int idx = rep * 256 + tid;
                int k = idx >> 5, c4 = idx & 31;
                *(float4*)&Vs[k * VS_STR + c4 * 4] =
                    *(const float4*)(Vg + (size_t)k * HD + c4 * 4);
            }
        }
        if (tid < 64) sks[tid] = g_ksq[(size_t)bh * L_ + j0 + tid];
        __syncthreads();

        float s[4][8];
#pragma unroll
        for (int i = 0; i < 4; i++)
#pragma unroll
            for (int j = 0; j < 8; j++) s[i][j] = 0.f;

#pragma unroll 8
        for (int kk = 0; kk < 128; kk++) {
            float4 qa  = *(const float4*)&Qs[kk * QS_STR + ty * 4];
            float4 kb0 = *(const float4*)&Ks[kk * KS_STR + tx * 8];
            float4 kb1 = *(const float4*)&Ks[kk * KS_STR + tx * 8 + 4];
            float a[4] = {qa.x, qa.y, qa.z, qa.w};
            float bb[8] = {kb0.x, kb0.y, kb0.z, kb0.w, kb1.x, kb1.y, kb1.z, kb1.w};
#pragma unroll
            for (int i = 0; i < 4; i++)
#pragma unroll
                for (int j = 0; j < 8; j++)
                    s[i][j] = fmaf(a[i], bb[j], s[i][j]);
        }

#pragma unroll
        for (int i = 0; i < 4; i++) {
            const int gq_ = qi * 128 + ty * 4 + i;
            const float qs = sqs[ty * 4 + i];
            float rm = -INFINITY;
#pragma unroll
            for (int j = 0; j < 8; j++) {
                int gk = j0 + tx * 8 + j;
                float sc = (2.f * s[i][j] - qs - sks[tx * 8 + j]) * inv_tau;
                sc = (gk > gq_) ? -INFINITY : sc;
                s[i][j] = sc;
                rm = fmaxf(rm, sc);
            }
            rm = fmaxf(rm, __shfl_xor_sync(0xffffffffu, rm, 1));
            rm = fmaxf(rm, __shfl_xor_sync(0xffffffffu, rm, 2));
            rm = fmaxf(rm, __shfl_xor_sync(0xffffffffu, rm, 4));
            float mnew = fmaxf(m_i[i], rm);
            float scale = __expf(m_i[i] - mnew);
            float rs = 0.f;
#pragma unroll
            for (int j = 0; j < 8; j++) {
                float p = __expf(s[i][j] - mnew);
                s[i][j] = p; rs += p;
            }
            rs += __shfl_xor_sync(0xffffffffu, rs, 1);
            rs += __shfl_xor_sync(0xffffffffu, rs, 2);
            rs += __shfl_xor_sync(0xffffffffu, rs, 4);
            l_i[i] = l_i[i] * scale + rs;
            m_i[i] = mnew;
#pragma unroll
            for (int cc = 0; cc < 16; cc++) O[i][cc] *= scale;
            *(float4*)&Ps[(ty * 4 + i) * PS_STR + tx * 8] =
                make_float4(s[i][0], s[i][1], s[i][2], s[i][3]);
            *(float4*)&Ps[(ty * 4 + i) * PS_STR + tx * 8 + 4] =
                make_float4(s[i][4], s[i][5], s[i][6], s[i][7]);
        }
        __syncthreads();

#pragma unroll 4
        for (int k = 0; k < 64; k++) {
            float4 v0 = *(const float4*)&Vs[k * VS_STR + tx * 16];
            float4 v1 = *(const float4*)&Vs[k * VS_STR + tx * 16 + 4];
            float4 v2 = *(const float4*)&Vs[k * VS_STR + tx * 16 + 8];
            float4 v3 = *(const float4*)&Vs[k * VS_STR + tx * 16 + 12];
            float vv[16] = {v0.x, v0.y, v0.z, v0.w, v1.x, v1.y, v1.z, v1.w,
                            v2.x, v2.y, v2.z, v2.w, v3.x, v3.y, v3.z, v3.w};
#pragma unroll
            for (int i = 0; i < 4; i++) {
                float p = Ps[(ty * 4 + i) * PS_STR + k];
#pragma unroll
                for (int cc = 0; cc < 16; cc++)
                    O[i][cc] = fmaf(p, vv[cc], O[i][cc]);
            }
        }
    }

#pragma unroll
    for (int i = 0; i < 4; i++) {
        float invl = 1.f / l_i[i];
        int gq_ = qi * 128 + ty * 4 + i;
        size_t off = (((size_t)b * L_ + gq_) * H_ + h) * HD + tx * 16;
        *(float4*)&g_att[off]      = make_float4(O[i][0] * invl,  O[i][1] * invl,
                                                 O[i][2] * invl,  O[i][3] * invl);
        *(float4*)&g_att[off + 4]  = make_float4(O[i][4] * invl,  O[i][5] * invl,
                                                 O[i][6] * invl,  O[i][7] * invl);
        *(float4*)&g_att[off + 8]  = make_float4(O[i][8] * invl,  O[i][9] * invl,
                                                 O[i][10] * invl, O[i][11] * invl);
        *(float4*)&g_att[off + 12] = make_float4(O[i][12] * invl, O[i][13] * invl,
                                                 O[i][14] * invl, O[i][15] * invl);
    }
}

// ---------------- launch --------------------------------------------------------
extern "C" void kernel_launch(void* const* d_in, const int* in_sizes, int n_in,
                              void* d_out, int out_size) {
    const float* x   = (const float*)d_in[0];
    const float* Wq  = (const float*)d_in[1];
    const float* Wk  = (const float*)d_in[2];
    const float* Wv  = (const float*)d_in[3];
    const float* Wo  = (const float*)d_in[4];
    const float* tau = (const float*)d_in[5];
    float* out = (float*)d_out;

    cudaFuncSetAttribute(flash_kernel, cudaFuncAttributeMaxDynamicSharedMemorySize,
                         FLASH_SMEM);

    rope_table_kernel<<<L_, 64>>>();
    sgemm_qkv_kernel<<<dim3(D_ / BN, (B_ * L_) / BM, 3), 256>>>(x, Wq, Wk, Wv);
    rope_kernel<<<dim3(L_, BH), 128>>>();
    flash_kernel<<<dim3(L_ / 128, BH), 256, FLASH_SMEM>>>(tau);
    sgemm_out_kernel<<<dim3(D_ / BN, (B_ * L_) / BM), 256>>>(Wo, out);
}

// round 8
// speedup vs baseline: 1.4879x; 1.0663x over previous
#include <cuda_runtime.h>
#include <math.h>
#include <stdint.h>

#define B_  4
#define L_  2048
#define D_  2048
#define H_  16
#define HD  128
#define BH  (B_*H_)

// ---------------- device scratch (allocation-free rule: __device__ globals) ----
__device__ float g_q[(size_t)BH * L_ * HD];     // (B,H,L,d)
__device__ float g_k[(size_t)BH * L_ * HD];     // (B,H,L,d)
__device__ float g_v[(size_t)BH * L_ * HD];     // (B,H,L,d)
__device__ float g_att[(size_t)B_ * L_ * D_];   // (B,L,H,d)
__device__ float g_qsq[BH * L_];
__device__ float g_ksq[BH * L_];
__device__ float g_cos[L_ * 64];
__device__ float g_sin[L_ * 64];

// ---------------- mma.sync helpers ---------------------------------------------
__device__ __forceinline__ uint32_t f2tf32(float x) {
    uint32_t r;
    asm("cvt.rna.tf32.f32 %0, %1;" : "=r"(r) : "f"(x));
    return r;
}
__device__ __forceinline__ void mma_tf32(float (&d)[4], const uint32_t (&a)[4],
                                         uint32_t b0, uint32_t b1) {
    asm volatile(
        "mma.sync.aligned.m16n8k8.row.col.f32.tf32.tf32.f32 "
        "{%0,%1,%2,%3}, {%4,%5,%6,%7}, {%8,%9}, {%0,%1,%2,%3};"
        : "+f"(d[0]), "+f"(d[1]), "+f"(d[2]), "+f"(d[3])
        : "r"(a[0]), "r"(a[1]), "r"(a[2]), "r"(a[3]), "r"(b0), "r"(b1));
}

// ---------------- RoPE tables (double-precision truth) ------------------------
__global__ void rope_table_kernel() {
    int l = blockIdx.x;
    int i = threadIdx.x;                       // 0..63
    double invf = exp(((double)(-2 * i) / 128.0) * log(10000.0));
    double th = (double)l * invf;
    double s, c;
    sincos(th, &s, &c);
    g_cos[l * 64 + i] = (float)c;
    g_sin[l * 64 + i] = (float)s;
}

// ---------------- GEMM core: C = A(MxK) * W(NxK)^T via mma.sync tf32 ------------
// 128x128 CTA tile, 256 threads, 8 warps in 4x2 grid, warp tile m32 x n64.
// Double-buffered BK=16 stages with register-staged global prefetch (no
// cp.async, static smem only — the proven-safe ingredient set). Smem holds
// tf32-converted bits so the MMA inner loop does raw LDS (no CVT).
#define BM 128
#define BN 128
#define BK 16
#define SAP 132   // padded smem row stride
#define GNIT (D_ / BK)   // 128

__device__ __forceinline__ void sgemm_compute_mma(const float* __restrict__ A,
                                                  const float* __restrict__ W,
                                                  int K, int bm, int bn,
                                                  float (&acc)[2][8][4]) {
    __shared__ uint32_t As[2][BK][SAP];   // As[buf][k][row], tf32 bits
    __shared__ uint32_t Ws[2][BK][SAP];   // Ws[buf][k][col], tf32 bits
    const int tid  = threadIdx.x;
    const int warp = tid >> 5, lane = tid & 31;
    const int wm0 = (warp >> 1) * 32, wn0 = (warp & 1) * 64;
    const int lr = lane >> 2;                           // 0..7
    const int lc = lane & 3;                            // 0..3
    const int ldr = tid >> 2;                           // 0..63
    const int ldc = (tid & 3) << 2;                     // 0,4,8,12

#pragma unroll
    for (int mt = 0; mt < 2; mt++)
#pragma unroll
        for (int nt = 0; nt < 8; nt++)
#pragma unroll
            for (int i = 0; i < 4; i++) acc[mt][nt][i] = 0.f;

    float4 va[2], vw[2];
    // preload tile 0 into registers
#pragma unroll
    for (int p = 0; p < 2; p++) {
        int r = ldr + p * 64;
        va[p] = *(const float4*)(A + (size_t)(bm + r) * K + ldc);
        vw[p] = *(const float4*)(W + (size_t)(bn + r) * K + ldc);
    }
    // stage into buffer 0
#pragma unroll
    for (int p = 0; p < 2; p++) {
        int r = ldr + p * 64;
        As[0][ldc + 0][r] = f2tf32(va[p].x); As[0][ldc + 1][r] = f2tf32(va[p].y);
        As[0][ldc + 2][r] = f2tf32(va[p].z); As[0][ldc + 3][r] = f2tf32(va[p].w);
        Ws[0][ldc + 0][r] = f2tf32(vw[p].x); Ws[0][ldc + 1][r] = f2tf32(vw[p].y);
        Ws[0][ldc + 2][r] = f2tf32(vw[p].z); Ws[0][ldc + 3][r] = f2tf32(vw[p].w);
    }
    __syncthreads();

    const int nit = K / BK;
    for (int it = 0; it < nit; it++) {
        const int cur = it & 1;

        // issue global loads for next tile (latency overlapped with MMAs below)
        if (it + 1 < nit) {
            const int k0 = (it + 1) * BK;
#pragma unroll
            for (int p = 0; p < 2; p++) {
                int r = ldr + p * 64;
                va[p] = *(const float4*)(A + (size_t)(bm + r) * K + k0 + ldc);
                vw[p] = *(const float4*)(W + (size_t)(bn + r) * K + k0 + ldc);
            }
        }

        // compute on current buffer
        const uint32_t (*Ac)[SAP] = As[cur];
        const uint32_t (*Wc)[SAP] = Ws[cur];
#pragma unroll
        for (int ks = 0; ks < BK / 8; ks++) {
            const int kb = ks * 8;
            uint32_t a[2][4];
#pragma unroll
            for (int mt = 0; mt < 2; mt++) {
                const int r = wm0 + mt * 16 + lr;
                a[mt][0] = Ac[kb + lc][r];
                a[mt][1] = Ac[kb + lc][r + 8];
                a[mt][2] = Ac[kb + lc + 4][r];
                a[mt][3] = Ac[kb + lc + 4][r + 8];
            }
#pragma unroll
            for (int nt = 0; nt < 8; nt++) {
                const int n = wn0 + nt * 8 + lr;
                uint32_t b0 = Wc[kb + lc][n];
                uint32_t b1 = Wc[kb + lc + 4][n];
                mma_tf32(acc[0][nt], a[0], b0, b1);
                mma_tf32(acc[1][nt], a[1], b0, b1);
            }
        }

        // stage next tile into the other buffer
        if (it + 1 < nit) {
            const int nxt = 1 - cur;
#pragma unroll
            for (int p = 0; p < 2; p++) {
                int r = ldr + p * 64;
                As[nxt][ldc + 0][r] = f2tf32(va[p].x);
                As[nxt][ldc + 1][r] = f2tf32(va[p].y);
                As[nxt][ldc + 2][r] = f2tf32(va[p].z);
                As[nxt][ldc + 3][r] = f2tf32(va[p].w);
                Ws[nxt][ldc + 0][r] = f2tf32(vw[p].x);
                Ws[nxt][ldc + 1][r] = f2tf32(vw[p].y);
                Ws[nxt][ldc + 2][r] = f2tf32(vw[p].z);
                Ws[nxt][ldc + 3][r] = f2tf32(vw[p].w);
            }
        }
        __syncthreads();
    }
}

// QKV projection: y = x @ W^T, stored remapped to (B,H,L,d)
__global__ void __launch_bounds__(256, 2) sgemm_qkv_kernel(const float* __restrict__ x,
                                                           const float* __restrict__ Wq,
                                                           const float* __restrict__ Wk,
                                                           const float* __restrict__ Wv) {
    const int z = blockIdx.z;
    const float* W = (z == 0) ? Wq : (z == 1) ? Wk : Wv;
    float* dst = (z == 0) ? g_q : (z == 1) ? g_k : g_v;
    float acc[2][8][4];
    const int bm = blockIdx.y * BM, bn = blockIdx.x * BN;
    sgemm_compute_mma(x, W, D_, bm, bn, acc);

    const int warp = threadIdx.x >> 5, lane = threadIdx.x & 31;
    const int wm0 = (warp >> 1) * 32, wn0 = (warp & 1) * 64;
    const int lr = lane >> 2, lc = lane & 3;
    const int h = bn >> 7;                      // 128-wide N tile == one head
#pragma unroll
    for (int mt = 0; mt < 2; mt++) {
        const int mlo = bm + wm0 + mt * 16 + lr;
#pragma unroll
        for (int nt = 0; nt < 8; nt++) {
            const int jj = wn0 + nt * 8 + 2 * lc;   // 0..126
#pragma unroll
            for (int half = 0; half < 2; half++) {
                const int m = mlo + half * 8;
                const int bb = m >> 11, l = m & 2047;
                float* p = dst + (((size_t)(bb * H_ + h) * L_ + l) * HD + jj);
                *(float2*)p = make_float2(acc[mt][nt][half * 2],
                                          acc[mt][nt][half * 2 + 1]);
            }
        }
    }
}

// Output projection: out = att @ Wo^T (plain row-major store)
__global__ void __launch_bounds__(256, 2) sgemm_out_kernel(const float* __restrict__ Wo,
                                                           float* __restrict__ C) {
    float acc[2][8][4];
    const int bm = blockIdx.y * BM, bn = blockIdx.x * BN;
    sgemm_compute_mma(g_att, Wo, D_, bm, bn, acc);

    const int warp = threadIdx.x >> 5, lane = threadIdx.x & 31;
    const int wm0 = (warp >> 1) * 32, wn0 = (warp & 1) * 64;
    const int lr = lane >> 2, lc = lane & 3;
#pragma unroll
    for (int mt = 0; mt < 2; mt++) {
        const int mlo = bm + wm0 + mt * 16 + lr;
#pragma unroll
        for (int nt = 0; nt < 8; nt++) {
            const int n0 = bn + wn0 + nt * 8 + 2 * lc;
#pragma unroll
            for (int half = 0; half < 2; half++) {
                const size_t m = mlo + half * 8;
                *(float2*)(C + m * D_ + n0) = make_float2(acc[mt][nt][half * 2],
                                                          acc[mt][nt][half * 2 + 1]);
            }
        }
    }
}

// ---------------- RoPE + sigmoid + row sum-of-squares --------------------------
__global__ void rope_kernel() {
    const int l = blockIdx.x, bh = blockIdx.y, j = threadIdx.x;
    const size_t base = ((size_t)bh * L_ + l) * HD;
    const float c = g_cos[l * 64 + (j & 63)];
    const float s = g_sin[l * 64 + (j & 63)];

    __shared__ float qr[128], kr[128];
    float qv = g_q[base + j], kv = g_k[base + j];
    qr[j] = qv; kr[j] = kv;
    __syncthreads();
    float qpart = (j < 64) ? -qr[j + 64] : qr[j - 64];
    float kpart = (j < 64) ? -kr[j + 64] : kr[j - 64];
    float qo = qv * c + qpart * s;
    float ko = kv * c + kpart * s;
    float qt = 1.f / (1.f + expf(-qo));
    float kt = 1.f / (1.f + expf(-ko));
    g_q[base + j] = qt;
    g_k[base + j] = kt;

    float q2 = qt * qt, k2 = kt * kt;
#pragma unroll
    for (int o = 16; o; o >>= 1) {
        q2 += __shfl_xor_sync(0xffffffffu, q2, o);
        k2 += __shfl_xor_sync(0xffffffffu, k2, o);
    }
    __shared__ float rq[4], rk[4];
    if ((j & 31) == 0) { rq[j >> 5] = q2; rk[j >> 5] = k2; }
    __syncthreads();
    if (j == 0) g_qsq[(size_t)bh * L_ + l] = rq[0] + rq[1] + rq[2] + rq[3];
    if (j == 1) g_ksq[(size_t)bh * L_ + l] = rk[0] + rk[1] + rk[2] + rk[3];
}

// ---------------- causal flash attention (fp32, proven R1) ----------------------
#define QS_STR 132
#define KS_STR 68
#define VS_STR 128
#define PS_STR 68
#define FLASH_SMEM ((128*QS_STR + 128*KS_STR + 64*VS_STR + 128*PS_STR + 128 + 64) * 4)

__global__ void __launch_bounds__(256) flash_kernel(const float* __restrict__ tau_p) {
    extern __shared__ float sm[];
    float* Qs  = sm;
    float* Ks  = Qs + 128 * QS_STR;
    float* Vs  = Ks + 128 * KS_STR;
    float* Ps  = Vs + 64 * VS_STR;
    float* sqs = Ps + 128 * PS_STR;
    float* sks = sqs + 128;

    const int qi = blockIdx.x;
    const int bh = blockIdx.y;
    const int b = bh >> 4, h = bh & 15;
    const int tid = threadIdx.x;
    const int lane = tid & 31, warp = tid >> 5;
    const int tx = tid & 7, ty = tid >> 3;

    float tr = tau_p[0];
    float tau = log1pf(expf(tr));
    tau = fminf(fmaxf(tau, 0.1f), 10.f);
    const float inv_tau = 1.f / tau;

    const size_t hbase = (size_t)bh * L_ * HD;
    const float* Qg = g_q + hbase + (size_t)qi * 128 * HD;

    {
        const int rl = lane >> 2;
        const int c4 = (warp << 2) + (lane & 3);
#pragma unroll
        for (int rep = 0; rep < 16; rep++) {
            int r = rep * 8 + rl;
            float4 v = *(const float4*)(Qg + (size_t)r * HD + c4 * 4);
            Qs[(c4 * 4 + 0) * QS_STR + r] = v.x;
            Qs[(c4 * 4 + 1) * QS_STR + r] = v.y;
            Qs[(c4 * 4 + 2) * QS_STR + r] = v.z;
            Qs[(c4 * 4 + 3) * QS_STR + r] = v.w;
        }
    }
    if (tid < 128) sqs[tid] = g_qsq[(size_t)bh * L_ + qi * 128 + tid];

    float m_i[4], l_i[4], O[4][16];
#pragma unroll
    for (int i = 0; i < 4; i++) {
        m_i[i] = -INFINITY; l_i[i] = 0.f;
#pragma unroll
        for (int cc = 0; cc < 16; cc++) O[i][cc] = 0.f;
    }

    const int ntk = 2 * qi + 2;
    for (int kt = 0; kt < ntk; kt++) {
        const int j0 = kt * 64;
        __syncthreads();

        {
            const int rl = lane >> 2;
            const int c4 = (warp << 2) + (lane & 3);
            const float* Kg = g_k + hbase + (size_t)j0 * HD;
#pragma unroll
            for (int rep = 0; rep < 8; rep++) {
                int r = rep * 8 + rl;
                float4 v = *(const float4*)(Kg + (size_t)r * HD + c4 * 4);
                Ks[(c4 * 4 + 0) * KS_STR + r] = v.x;
                Ks[(c4 * 4 + 1) * KS_STR + r] = v.y;
                Ks[(c4 * 4 + 2) * KS_STR + r] = v.z;
                Ks[(c4 * 4 + 3) * KS_STR + r] = v.w;
            }
        }
        {
            const float* Vg = g_v + hbase + (size_t)j0 * HD;
#pragma unroll
            for (int rep = 0; rep < 8; rep++) {
                int idx = rep * 256 + tid;
                int k = idx >> 5, c4 = idx & 31;
                *(float4*)&Vs[k * VS_STR + c4 * 4] =
                    *(const float4*)(Vg + (size_t)k * HD + c4 * 4);
            }
        }
        if (tid < 64) sks[tid] = g_ksq[(size_t)bh * L_ + j0 + tid];
        __syncthreads();

        float s[4][8];
#pragma unroll
        for (int i = 0; i < 4; i++)
#pragma unroll
            for (int j = 0; j < 8; j++) s[i][j] = 0.f;

#pragma unroll 8
        for (int kk = 0; kk < 128; kk++) {
            float4 qa  = *(const float4*)&Qs[kk * QS_STR + ty * 4];
            float4 kb0 = *(const float4*)&Ks[kk * KS_STR + tx * 8];
            float4 kb1 = *(const float4*)&Ks[kk * KS_STR + tx * 8 + 4];
            float a[4] = {qa.x, qa.y, qa.z, qa.w};
            float bb[8] = {kb0.x, kb0.y, kb0.z, kb0.w, kb1.x, kb1.y, kb1.z, kb1.w};
#pragma unroll
            for (int i = 0; i < 4; i++)
#pragma unroll
                for (int j = 0; j < 8; j++)
                    s[i][j] = fmaf(a[i], bb[j], s[i][j]);
        }

#pragma unroll
        for (int i = 0; i < 4; i++) {
            const int gq_ = qi * 128 + ty * 4 + i;
            const float qs = sqs[ty * 4 + i];
            float rm = -INFINITY;
#pragma unroll
            for (int j = 0; j < 8; j++) {
                int gk = j0 + tx * 8 + j;
                float sc = (2.f * s[i][j] - qs - sks[tx * 8 + j]) * inv_tau;
                sc = (gk > gq_) ? -INFINITY : sc;
                s[i][j] = sc;
                rm = fmaxf(rm, sc);
            }
            rm = fmaxf(rm, __shfl_xor_sync(0xffffffffu, rm, 1));
            rm = fmaxf(rm, __shfl_xor_sync(0xffffffffu, rm, 2));
            rm = fmaxf(rm, __shfl_xor_sync(0xffffffffu, rm, 4));
            float mnew = fmaxf(m_i[i], rm);
            float scale = __expf(m_i[i] - mnew);
            float rs = 0.f;
#pragma unroll
            for (int j = 0; j < 8; j++) {
                float p = __expf(s[i][j] - mnew);
                s[i][j] = p; rs += p;
            }
            rs += __shfl_xor_sync(0xffffffffu, rs, 1);
            rs += __shfl_xor_sync(0xffffffffu, rs, 2);
            rs += __shfl_xor_sync(0xffffffffu, rs, 4);
            l_i[i] = l_i[i] * scale + rs;
            m_i[i] = mnew;
#pragma unroll
            for (int cc = 0; cc < 16; cc++) O[i][cc] *= scale;
            *(float4*)&Ps[(ty * 4 + i) * PS_STR + tx * 8] =
                make_float4(s[i][0], s[i][1], s[i][2], s[i][3]);
            *(float4*)&Ps[(ty * 4 + i) * PS_STR + tx * 8 + 4] =
                make_float4(s[i][4], s[i][5], s[i][6], s[i][7]);
        }
        __syncthreads();

#pragma unroll 4
        for (int k = 0; k < 64; k++) {
            float4 v0 = *(const float4*)&Vs[k * VS_STR + tx * 16];
            float4 v1 = *(const float4*)&Vs[k * VS_STR + tx * 16 + 4];
            float4 v2 = *(const float4*)&Vs[k * VS_STR + tx * 16 + 8];
            float4 v3 = *(const float4*)&Vs[k * VS_STR + tx * 16 + 12];
            float vv[16] = {v0.x, v0.y, v0.z, v0.w, v1.x, v1.y, v1.z, v1.w,
                            v2.x, v2.y, v2.z, v2.w, v3.x, v3.y, v3.z, v3.w};
#pragma unroll
            for (int i = 0; i < 4; i++) {
                float p = Ps[(ty * 4 + i) * PS_STR + k];
#pragma unroll
                for (int cc = 0; cc < 16; cc++)
                    O[i][cc] = fmaf(p, vv[cc], O[i][cc]);
            }
        }
    }

#pragma unroll
    for (int i = 0; i < 4; i++) {
        float invl = 1.f / l_i[i];
        int gq_ = qi * 128 + ty * 4 + i;
        size_t off = (((size_t)b * L_ + gq_) * H_ + h) * HD + tx * 16;
        *(float4*)&g_att[off]      = make_float4(O[i][0] * invl,  O[i][1] * invl,
                                                 O[i][2] * invl,  O[i][3] * invl);
        *(float4*)&g_att[off + 4]  = make_float4(O[i][4] * invl,  O[i][5] * invl,
                                                 O[i][6] * invl,  O[i][7] * invl);
        *(float4*)&g_att[off + 8]  = make_float4(O[i][8] * invl,  O[i][9] * invl,
                                                 O[i][10] * invl, O[i][11] * invl);
        *(float4*)&g_att[off + 12] = make_float4(O[i][12] * invl, O[i][13] * invl,
                                                 O[i][14] * invl, O[i][15] * invl);
    }
}

// ---------------- launch --------------------------------------------------------
extern "C" void kernel_launch(void* const* d_in, const int* in_sizes, int n_in,
                              void* d_out, int out_size) {
    const float* x   = (const float*)d_in[0];
    const float* Wq  = (const float*)d_in[1];
    const float* Wk  = (const float*)d_in[2];
    const float* Wv  = (const float*)d_in[3];
    const float* Wo  = (const float*)d_in[4];
    const float* tau = (const float*)d_in[5];
    float* out = (float*)d_out;

    cudaFuncSetAttribute(flash_kernel, cudaFuncAttributeMaxDynamicSharedMemorySize,
                         FLASH_SMEM);

    rope_table_kernel<<<L_, 64>>>();
    sgemm_qkv_kernel<<<dim3(D_ / BN, (B_ * L_) / BM, 3), 256>>>(x, Wq, Wk, Wv);
    rope_kernel<<<dim3(L_, BH), 128>>>();
    flash_kernel<<<dim3(L_ / 128, BH), 256, FLASH_SMEM>>>(tau);
    sgemm_out_kernel<<<dim3(D_ / BN, (B_ * L_) / BM), 256>>>(Wo, out);
}